// round 16
// baseline (speedup 1.0000x reference)
#include <cuda_runtime.h>
#include <cstdint>

// DynamicTopGate, persistent fused kernel (round 16).
//
// Invariants (do not violate):
//  - NO inline-asm in the GEMM loop (caps BW ~1 TB/s).
//  - Round-12 GEMM config protected: 2 rows/warp, scalar fmaf, unroll 4,
//    __ldcs x / __ldg W1, <=96 regs, (128,5).
//  - Warp-parallel epilogue (round 12) ~1us, warp-local (no smem).
// Round-15 showed nothing saturated (latency/duty-cycle bound) and the grid
// runs 2.77 partial waves. This round: persistent grid-stride -- exactly
// 148*5=740 blocks, each looping over row-groups. Kills the wave tail and
// keeps the memory pipe fed across group boundaries. Inner loop untouched.

#define IN_DIM 2048
#define NE     16

typedef unsigned long long u64;

__global__ void __launch_bounds__(128, 5)
gate_kernel(const float* __restrict__ x, const float* __restrict__ W1,
            const float* __restrict__ W2, float* __restrict__ out,
            int B, int numGroups)
{
    const int lane = threadIdx.x & 31;
    const int wIn  = threadIdx.x >> 5;
    const unsigned FULL = 0xffffffffu;

    const float4* wp = reinterpret_cast<const float4*>(W1) + lane;

    // Epilogue constants hoisted out of the persistent loop.
    const int hw = lane >> 4;
    const int le = lane & 15;
    const int hbase = hw << 4;
    float wr[NE];
    {
        const float4* W2v = reinterpret_cast<const float4*>(W2) + le * (NE / 4);
        #pragma unroll
        for (int q = 0; q < NE / 4; ++q) {
            float4 w = __ldg(W2v + q);
            wr[4 * q + 0] = w.x; wr[4 * q + 1] = w.y;
            wr[4 * q + 2] = w.z; wr[4 * q + 3] = w.w;
        }
    }
    float* oidx  = out;
    float* osc   = out + (size_t)B * 8;
    float* omask = out + (size_t)B * 16;
    float* okv   = out + (size_t)B * 24;

    // Persistent loop: each block strides over 8-row groups.
    for (int g = blockIdx.x; g < numGroups; g += gridDim.x) {
        const int row0 = g * 8 + wIn * 2;        // this warp's 2 rows
        if (row0 >= B) continue;

        const float4* x0 = reinterpret_cast<const float4*>(x + (size_t)row0 * IN_DIM) + lane;
        const float4* x1 = x0 + (IN_DIM / 4);

        float acc0[NE], acc1[NE];
        #pragma unroll
        for (int e = 0; e < NE; ++e) { acc0[e] = 0.0f; acc1[e] = 0.0f; }

        // Round-8/12 proven loop: 16 chunks of 128 columns, unroll 4 so
        // ptxas front-batches 8 LDG.128 x-loads per body. DO NOT add asm.
        #pragma unroll 4
        for (int c = 0; c < IN_DIM / 128; ++c) {
            float4 a0 = __ldcs(x0 + c * 32);     // stream x: keep W1 in L1
            float4 a1 = __ldcs(x1 + c * 32);
            #pragma unroll
            for (int e = 0; e < NE; ++e) {
                float4 w = __ldg(wp + e * (IN_DIM / 4) + c * 32);  // W1 L1-resident
                acc0[e] = fmaf(a0.x, w.x, fmaf(a0.y, w.y,
                          fmaf(a0.z, w.z, fmaf(a0.w, w.w, acc0[e]))));
                acc1[e] = fmaf(a1.x, w.x, fmaf(a1.y, w.y,
                          fmaf(a1.z, w.z, fmaf(a1.w, w.w, acc1[e]))));
            }
        }

        // Butterfly-reduce each accumulator across the warp.
        #pragma unroll
        for (int e = 0; e < NE; ++e) {
            #pragma unroll
            for (int off = 16; off > 0; off >>= 1) {
                acc0[e] += __shfl_xor_sync(FULL, acc0[e], off);
                acc1[e] += __shfl_xor_sync(FULL, acc1[e], off);
            }
        }

        // ---------- warp-parallel epilogue (round-12, warp-local) ----------
        const int row = row0 + hw;

        // Distribute: lane le owns expert le of its half-warp's row.
        float sv = 0.0f;
        #pragma unroll
        for (int e = 0; e < NE; ++e)
            if (le == e) sv = hw ? acc1[e] : acc0[e];

        float h = tanhf(sv);

        // logits[le] = (sum_e h[e] * W2[le, e]) / 0.7 ; gather h via shfl.
        float logit = 0.0f;
        #pragma unroll
        for (int e = 0; e < NE; ++e) {
            float he = __shfl_sync(FULL, h, hbase + e);
            logit = fmaf(he, wr[e], logit);
        }
        float v = logit / 0.7f;

        // Pack key: monotone float high, (15-idx) low -> stable descending.
        unsigned iv = __float_as_uint(v);
        unsigned mk = iv ^ (unsigned)(((int)iv >> 31) | 0x80000000);
        u64 key = ((u64)mk << 32) | (unsigned)(15 - le);

        // Bitonic sort, descending, 16 lanes per half-warp.
        #pragma unroll
        for (int k2 = 2; k2 <= 16; k2 <<= 1) {
            #pragma unroll
            for (int j = k2 >> 1; j > 0; j >>= 1) {
                u64 other = __shfl_xor_sync(FULL, key, j);
                bool lowlane = ((le & j) == 0);
                bool dirup   = ((le & k2) == 0);
                bool wantMax = (lowlane == dirup);
                bool take = wantMax ? (other > key) : (other < key);
                if (take) key = other;
            }
        }

        int sidx = 15 - (int)(key & 0xFu);
        unsigned smk = (unsigned)(key >> 32);
        unsigned siv = (smk & 0x80000000u) ? (smk ^ 0x80000000u) : ~smk;
        float sval = __uint_as_float(siv);

        // Softmax over sorted logits (max at lane hbase).
        float m = __shfl_sync(FULL, sval, hbase);
        float p = expf(sval - m);
        float ssum = p;
        #pragma unroll
        for (int off = 8; off > 0; off >>= 1)
            ssum += __shfl_xor_sync(FULL, ssum, off);
        p *= (1.0f / ssum);

        // Inclusive cumsum within half-warp.
        float cum = p;
        #pragma unroll
        for (int off = 1; off < 16; off <<= 1) {
            float t = __shfl_up_sync(FULL, cum, off);
            if (le >= off) cum += t;
        }

        // k = first position where cum >= 0.92 (else 16).
        unsigned bal = __ballot_sync(FULL, cum >= 0.92f);
        unsigned half_mask = (bal >> hbase) & 0xFFFFu;
        int k = half_mask ? __ffs(half_mask) : NE;

        float p1 = __shfl_sync(FULL, p, hbase + 0);
        float p2 = __shfl_sync(FULL, p, hbase + 1);
        float p3 = __shfl_sync(FULL, p, hbase + 2);
        if (p1 >= 0.46f && (p1 - p2) >= 0.1f) k = 1;
        if (k > 2 && ((p1 + p2) >= 0.82f || p3 <= 0.12f || (p2 - p3) <= 0.03f)) k = 2;
        if (k < 1) k = 1;
        if (k > 3) k = 3;

        if (le < 8 && row < B) {
            float msk = (le < k) ? 1.0f : 0.0f;
            oidx[row * 8 + le]  = (float)sidx;
            osc[row * 8 + le]   = p * msk;
            omask[row * 8 + le] = msk;
            if (le == 0) okv[row] = (float)k;
        }
    }
}

extern "C" void kernel_launch(void* const* d_in, const int* in_sizes, int n_in,
                              void* d_out, int out_size)
{
    const float* x  = (const float*)d_in[0];
    const float* W1 = (const float*)d_in[1];
    const float* W2 = (const float*)d_in[2];
    float* out = (float*)d_out;

    int B = in_sizes[0] / IN_DIM;                 // 16384
    int numGroups = (B + 7) / 8;                  // 2048

    // Persistent: exactly one full wave (148 SMs x 5 resident blocks).
    int blocks = 148 * 5;                         // 740
    if (blocks > numGroups) blocks = numGroups;
    gate_kernel<<<blocks, 128>>>(x, W1, W2, out, B, numGroups);
}